// round 1
// baseline (speedup 1.0000x reference)
#include <cuda_runtime.h>
#include <math.h>

#define N_NODES 50000
#define E_EDGES 800000
#define DIN     128
#define NH      4
#define ND      16
#define HD      64      // NH*ND
#define NEG_SLOPE 0.2f

// ---------------- scratch (static device globals; no allocation) ----------------
__device__ __align__(16) float g_feat [N_NODES * HD];   // projected features [N,H,D]
__device__ float g_el   [N_NODES * NH];                 // per-node left attn half
__device__ float g_er   [N_NODES * NH];                 // per-node right attn half
__device__ float g_m    [N_NODES * NH];                 // segment max
__device__ float g_den  [N_NODES * NH];                 // segment sum of exp
__device__ float g_e    [E_EDGES * NH];                 // per-edge logits -> exp
__device__ __align__(16) float g_acc  [N_NODES * HD];   // aggregation accumulator

// ---------------- helpers ----------------
__device__ __forceinline__ void atomicMaxFloat(float* addr, float val) {
    // works for mixed signs: nonneg floats order as signed ints,
    // negative floats reverse-order as unsigned ints
    if (val >= 0.0f) atomicMax((int*)addr, __float_as_int(val));
    else             atomicMin((unsigned int*)addr, __float_as_uint(val));
}

// ---------------- pass 0: init ----------------
__global__ void k_init() {
    int idx = blockIdx.x * blockDim.x + threadIdx.x;
    if (idx < N_NODES * HD) g_acc[idx] = 0.0f;
    if (idx < N_NODES * NH) {
        g_m[idx]   = __int_as_float(0xff800000); // -inf
        g_den[idx] = 0.0f;
    }
}

// ---------------- pass 1: feat = h @ W, plus el/er reductions ----------------
// one block per node, 64 threads (one per output column h*16+d)
__global__ void k_proj(const float* __restrict__ h, const float* __restrict__ W,
                       const float* __restrict__ attn_l, const float* __restrict__ attn_r) {
    __shared__ float sh[DIN];
    int n = blockIdx.x;
    int t = threadIdx.x;             // 0..63
    // cooperative load of the node's input row (128 floats, float2 per thread)
    ((float2*)sh)[t] = ((const float2*)(h + (size_t)n * DIN))[t];
    __syncthreads();

    float acc = 0.0f;
#pragma unroll 8
    for (int k = 0; k < DIN; k++)
        acc += sh[k] * W[k * HD + t];

    g_feat[n * HD + t] = acc;

    int hh = t >> 4;                 // head
    int dd = t & 15;                 // dim within head
    float pl = acc * attn_l[hh * ND + dd];
    float pr = acc * attn_r[hh * ND + dd];
    // reduce within each 16-lane group (one head)
#pragma unroll
    for (int o = 8; o > 0; o >>= 1) {
        pl += __shfl_xor_sync(0xffffffffu, pl, o, 16);
        pr += __shfl_xor_sync(0xffffffffu, pr, o, 16);
    }
    if (dd == 0) {
        g_el[n * NH + hh] = pl;
        g_er[n * NH + hh] = pr;
    }
}

// ---------------- pass 2: edge logits + segment max ----------------
// one thread per (edge, head)
__global__ void k_logit(const int* __restrict__ src, const int* __restrict__ dst) {
    int idx = blockIdx.x * blockDim.x + threadIdx.x;
    if (idx >= E_EDGES * NH) return;
    int e  = idx >> 2;
    int hh = idx & 3;
    int s = src[e];
    int d = dst[e];
    float x = g_el[s * NH + hh] + g_er[d * NH + hh];
    x = (x > 0.0f) ? x : NEG_SLOPE * x;
    g_e[idx] = x;
    atomicMaxFloat(&g_m[d * NH + hh], x);
}

// ---------------- pass 3: exp + segment sum ----------------
__global__ void k_expsum(const int* __restrict__ dst) {
    int idx = blockIdx.x * blockDim.x + threadIdx.x;
    if (idx >= E_EDGES * NH) return;
    int e  = idx >> 2;
    int hh = idx & 3;
    int d = dst[e];
    float ex = __expf(g_e[idx] - g_m[d * NH + hh]);
    g_e[idx] = ex;
    atomicAdd(&g_den[d * NH + hh], ex);
}

// ---------------- pass 4: weighted scatter-aggregate ----------------
// 16 threads per edge; each thread handles 4 consecutive output floats (one
// red.global.add.v4.f32 -> 1/4 the atomic op count)
__global__ void k_scatter(const int* __restrict__ src, const int* __restrict__ dst) {
    int idx = blockIdx.x * blockDim.x + threadIdx.x;
    if (idx >= E_EDGES * 16) return;
    int e = idx >> 4;
    int j = idx & 15;                // 0..15 -> head = j>>2, 4 dims
    int hh = j >> 2;
    int s = src[e];
    int d = dst[e];
    float a = g_e[e * NH + hh] / g_den[d * NH + hh];
    const float4 f = *(const float4*)(&g_feat[s * HD + j * 4]);
    float* p = &g_acc[d * HD + j * 4];
    asm volatile("red.global.add.v4.f32 [%0], {%1, %2, %3, %4};"
                 :: "l"(p), "f"(a * f.x), "f"(a * f.y), "f"(a * f.z), "f"(a * f.w)
                 : "memory");
}

// ---------------- pass 5: mean over heads ----------------
__global__ void k_final(float* __restrict__ out) {
    int idx = blockIdx.x * blockDim.x + threadIdx.x;
    if (idx >= N_NODES * ND) return;
    int n  = idx >> 4;
    int dd = idx & 15;
    const float* base = &g_acc[n * HD];
    out[idx] = 0.25f * (base[dd] + base[ND + dd] + base[2 * ND + dd] + base[3 * ND + dd]);
}

// ---------------- launch ----------------
extern "C" void kernel_launch(void* const* d_in, const int* in_sizes, int n_in,
                              void* d_out, int out_size) {
    const float* h      = (const float*)d_in[0];
    const float* W      = (const float*)d_in[1];
    const float* attn_l = (const float*)d_in[2];
    const float* attn_r = (const float*)d_in[3];
    const int*   src    = (const int*)d_in[4];
    const int*   dst    = (const int*)d_in[5];
    float* out = (float*)d_out;

    k_init   <<<(N_NODES * HD + 255) / 256, 256>>>();
    k_proj   <<<N_NODES, 64>>>(h, W, attn_l, attn_r);
    k_logit  <<<(E_EDGES * NH + 255) / 256, 256>>>(src, dst);
    k_expsum <<<(E_EDGES * NH + 255) / 256, 256>>>(dst);
    k_scatter<<<(E_EDGES * 16 + 255) / 256, 256>>>(src, dst);
    k_final  <<<(N_NODES * ND + 255) / 256, 256>>>(out);
}

// round 2
// speedup vs baseline: 1.7544x; 1.7544x over previous
#include <cuda_runtime.h>
#include <math.h>

#define N_NODES 50000
#define E_EDGES 800000
#define DIN     128
#define NH      4
#define ND      16
#define HD      64      // NH*ND
#define NEG_SLOPE 0.2f

// ---------------- scratch (static device globals; no allocation) ----------------
__device__ __align__(16) float g_feat [N_NODES * HD];   // projected features [N,H,D]
__device__ __align__(16) float g_el   [N_NODES * NH];   // per-node left attn half
__device__ __align__(16) float g_er   [N_NODES * NH];   // per-node right attn half
__device__ __align__(16) float g_den  [N_NODES * NH];   // segment sum of exp (unshifted)
__device__ __align__(16) float g_acc  [N_NODES * HD];   // aggregation accumulator (unnormalized)

// ---------------- pass 0: init ----------------
__global__ void k_init() {
    int idx = blockIdx.x * blockDim.x + threadIdx.x;
    if (idx < N_NODES * HD) g_acc[idx] = 0.0f;
    if (idx < N_NODES * NH) g_den[idx] = 0.0f;
}

// ---------------- pass 1: feat = h @ W (tiled GEMM) + el/er epilogue ----------------
// Block: 256 threads, 64-node M-tile, full N=64, K split into two 64-wide phases.
// Each thread computes a 4x4 (nodes x cols) micro-tile: 8 LDS.128 per 64 FMA.
#define MT 64
#define KP 64               // k-phase width
#define PW 68               // smem row pitch (floats), 16B-aligned, conflict-mitigating

__global__ __launch_bounds__(256) void k_proj(const float* __restrict__ h,
                                              const float* __restrict__ W,
                                              const float* __restrict__ attn_l,
                                              const float* __restrict__ attn_r) {
    __shared__ float w_s[KP * PW];     // [kk][col]
    __shared__ float h_s[MT * PW];     // [ln][kk]

    const int tid = threadIdx.x;
    const int tc  = tid & 15;          // col-group: cols 4*tc .. 4*tc+3
    const int tn  = tid >> 4;          // node-group: nodes 4*tn .. 4*tn+3
    const int nb  = blockIdx.x * MT;

    float acc[4][4];
#pragma unroll
    for (int i = 0; i < 4; i++)
#pragma unroll
        for (int j = 0; j < 4; j++) acc[i][j] = 0.0f;

    for (int kb = 0; kb < DIN; kb += KP) {
        __syncthreads();   // protect smem reuse across phases
        // load W[kb..kb+63][0..63]  (1024 float4, 4 per thread)
#pragma unroll
        for (int r = 0; r < 4; r++) {
            int idx = tid + r * 256;           // float4 index
            int kk = idx >> 4, c4 = (idx & 15) << 2;
            float4 v = *(const float4*)(W + (size_t)(kb + kk) * HD + c4);
            *(float4*)(w_s + kk * PW + c4) = v;
        }
        // load h[nb..nb+63][kb..kb+63]
#pragma unroll
        for (int r = 0; r < 4; r++) {
            int idx = tid + r * 256;
            int ln = idx >> 4, c4 = (idx & 15) << 2;
            float4 v = make_float4(0.f, 0.f, 0.f, 0.f);
            if (nb + ln < N_NODES)
                v = *(const float4*)(h + (size_t)(nb + ln) * DIN + kb + c4);
            *(float4*)(h_s + ln * PW + c4) = v;
        }
        __syncthreads();

#pragma unroll
        for (int kc = 0; kc < KP / 4; kc++) {
            const int k = kc * 4;
            float4 w0 = *(const float4*)(w_s + (k + 0) * PW + tc * 4);
            float4 w1 = *(const float4*)(w_s + (k + 1) * PW + tc * 4);
            float4 w2 = *(const float4*)(w_s + (k + 2) * PW + tc * 4);
            float4 w3 = *(const float4*)(w_s + (k + 3) * PW + tc * 4);
#pragma unroll
            for (int i = 0; i < 4; i++) {
                float4 hv = *(const float4*)(h_s + (tn * 4 + i) * PW + k);
                acc[i][0] += hv.x * w0.x + hv.y * w1.x + hv.z * w2.x + hv.w * w3.x;
                acc[i][1] += hv.x * w0.y + hv.y * w1.y + hv.z * w2.y + hv.w * w3.y;
                acc[i][2] += hv.x * w0.z + hv.y * w1.z + hv.z * w2.z + hv.w * w3.z;
                acc[i][3] += hv.x * w0.w + hv.y * w1.w + hv.z * w2.w + hv.w * w3.w;
            }
        }
    }

    // epilogue: store feat, compute el/er
    const int head = tc >> 2;                   // all 4 cols of this thread in one head
    const int dbase = head * ND + (tc & 3) * 4; // dim within head
    const float4 al = *(const float4*)(attn_l + dbase);
    const float4 ar = *(const float4*)(attn_r + dbase);

#pragma unroll
    for (int i = 0; i < 4; i++) {
        int node = nb + tn * 4 + i;
        if (node >= N_NODES) continue;
        float4 f = make_float4(acc[i][0], acc[i][1], acc[i][2], acc[i][3]);
        *(float4*)(g_feat + (size_t)node * HD + tc * 4) = f;

        float pl = f.x * al.x + f.y * al.y + f.z * al.z + f.w * al.w;
        float pr = f.x * ar.x + f.y * ar.y + f.z * ar.z + f.w * ar.w;
        // reduce across the 4 consecutive lanes covering this head
        pl += __shfl_xor_sync(0xffffffffu, pl, 1);
        pl += __shfl_xor_sync(0xffffffffu, pl, 2);
        pr += __shfl_xor_sync(0xffffffffu, pr, 1);
        pr += __shfl_xor_sync(0xffffffffu, pr, 2);
        if ((tc & 3) == 0) {
            g_el[node * NH + head] = pl;
            g_er[node * NH + head] = pr;
        }
    }
}

// ---------------- pass 2: fused edge pass ----------------
// 16 threads per edge. Each lane: computes the (unshifted) exp of its head's
// logit inline, scatters ex*feat4 via red.v4, and one lane per head scatters ex
// into the denominator. Softmax shift-invariance makes the max pass unnecessary
// (logits are O(±2) here; fp32 exp is safe).
__global__ __launch_bounds__(256) void k_scatter(const int* __restrict__ src,
                                                 const int* __restrict__ dst) {
    int idx = blockIdx.x * blockDim.x + threadIdx.x;
    int e = idx >> 4;
    if (e >= E_EDGES) return;
    int j  = idx & 15;       // 0..15: head = j>>2, 4 dims each
    int hh = j >> 2;
    int s = src[e];
    int d = dst[e];

    float x = g_el[s * NH + hh] + g_er[d * NH + hh];
    x = (x > 0.0f) ? x : NEG_SLOPE * x;
    float ex = __expf(x);

    if ((j & 3) == 0)
        atomicAdd(&g_den[d * NH + hh], ex);   // no return value used -> RED

    float4 f = *(const float4*)(&g_feat[(size_t)s * HD + j * 4]);
    float* p = &g_acc[(size_t)d * HD + j * 4];
    asm volatile("red.global.add.v4.f32 [%0], {%1, %2, %3, %4};"
                 :: "l"(p), "f"(ex * f.x), "f"(ex * f.y), "f"(ex * f.z), "f"(ex * f.w)
                 : "memory");
}

// ---------------- pass 3: normalize + mean over heads ----------------
__global__ void k_final(float* __restrict__ out) {
    int idx = blockIdx.x * blockDim.x + threadIdx.x;
    if (idx >= N_NODES * ND) return;
    int n  = idx >> 4;
    int dd = idx & 15;
    const float* accb = &g_acc[(size_t)n * HD];
    const float* denb = &g_den[n * NH];
    float sum = 0.0f;
#pragma unroll
    for (int hh = 0; hh < NH; hh++) {
        float den = denb[hh];
        float r = (den > 0.0f) ? (1.0f / den) : 0.0f;   // empty segment -> 0
        sum += accb[hh * ND + dd] * r;
    }
    out[idx] = 0.25f * sum;
}

// ---------------- launch ----------------
extern "C" void kernel_launch(void* const* d_in, const int* in_sizes, int n_in,
                              void* d_out, int out_size) {
    const float* h      = (const float*)d_in[0];
    const float* W      = (const float*)d_in[1];
    const float* attn_l = (const float*)d_in[2];
    const float* attn_r = (const float*)d_in[3];
    const int*   src    = (const int*)d_in[4];
    const int*   dst    = (const int*)d_in[5];
    float* out = (float*)d_out;

    k_init   <<<(N_NODES * HD + 255) / 256, 256>>>();
    k_proj   <<<(N_NODES + MT - 1) / MT, 256>>>(h, W, attn_l, attn_r);
    k_scatter<<<(E_EDGES * 16 + 255) / 256, 256>>>(src, dst);
    k_final  <<<(N_NODES * ND + 255) / 256, 256>>>(out);
}

// round 3
// speedup vs baseline: 1.8356x; 1.0463x over previous
#include <cuda_runtime.h>
#include <math.h>

#define N_NODES 50000
#define E_EDGES 800000
#define DIN     128
#define NH      4
#define ND      16
#define HD      64      // NH*ND
#define NEG_SLOPE 0.2f

typedef unsigned long long u64;

// ---------------- scratch (static device globals; no allocation) ----------------
__device__ __align__(16) float g_feat [N_NODES * HD];   // projected features [N,H,D]
__device__ __align__(16) float g_el   [N_NODES * NH];   // per-node left attn half
__device__ __align__(16) float g_er   [N_NODES * NH];   // per-node right attn half
__device__ __align__(16) float g_den  [N_NODES * NH];   // segment sum of exp (unshifted)
__device__ __align__(16) float g_acc  [N_NODES * HD];   // aggregation accumulator (unnormalized)

// ---------------- f32x2 packed-FMA helpers (sm_100+ FFMA2) ----------------
__device__ __forceinline__ u64 pk2(float x, float y) {
    u64 r; asm("mov.b64 %0, {%1, %2};" : "=l"(r) : "f"(x), "f"(y)); return r;
}
__device__ __forceinline__ void upk2(u64 v, float& x, float& y) {
    asm("mov.b64 {%0, %1}, %2;" : "=f"(x), "=f"(y) : "l"(v));
}
__device__ __forceinline__ void ffma2(u64& c, u64 a, u64 b) {
    asm("fma.rn.f32x2 %0, %1, %2, %0;" : "+l"(c) : "l"(a), "l"(b));
}

// ---------------- pass 0: init ----------------
__global__ void k_init() {
    int idx = blockIdx.x * blockDim.x + threadIdx.x;
    if (idx < N_NODES * HD) g_acc[idx] = 0.0f;
    if (idx < N_NODES * NH) g_den[idx] = 0.0f;
}

// ---------------- pass 1: feat = h @ W (tiled GEMM, FFMA2 core) + el/er ----------------
#define MT 64
#define KP 64               // k-phase width
#define PW 68               // smem row pitch (floats)

__global__ __launch_bounds__(256) void k_proj(const float* __restrict__ h,
                                              const float* __restrict__ W,
                                              const float* __restrict__ attn_l,
                                              const float* __restrict__ attn_r) {
    __shared__ float w_s[KP * PW];     // [kk][col]
    __shared__ float h_s[MT * PW];     // [ln][kk]

    const int tid = threadIdx.x;
    const int tc  = tid & 15;          // col-group: cols 4*tc .. 4*tc+3
    const int tn  = tid >> 4;          // node-group: nodes 4*tn .. 4*tn+3
    const int nb  = blockIdx.x * MT;

    // acc2[i][p]: packed pair p (cols 4tc+2p, 4tc+2p+1) for node row i
    u64 acc2[4][2];
#pragma unroll
    for (int i = 0; i < 4; i++) { acc2[i][0] = 0ull; acc2[i][1] = 0ull; }

    for (int kb = 0; kb < DIN; kb += KP) {
        __syncthreads();
#pragma unroll
        for (int r = 0; r < 4; r++) {
            int idx = tid + r * 256;           // float4 index
            int kk = idx >> 4, c4 = (idx & 15) << 2;
            float4 v = *(const float4*)(W + (size_t)(kb + kk) * HD + c4);
            *(float4*)(w_s + kk * PW + c4) = v;
        }
#pragma unroll
        for (int r = 0; r < 4; r++) {
            int idx = tid + r * 256;
            int ln = idx >> 4, c4 = (idx & 15) << 2;
            float4 v = make_float4(0.f, 0.f, 0.f, 0.f);
            if (nb + ln < N_NODES)
                v = *(const float4*)(h + (size_t)(nb + ln) * DIN + kb + c4);
            *(float4*)(h_s + ln * PW + c4) = v;
        }
        __syncthreads();

#pragma unroll
        for (int kc = 0; kc < KP / 4; kc++) {
            const int k = kc * 4;
            float4 w0 = *(const float4*)(w_s + (k + 0) * PW + tc * 4);
            float4 w1 = *(const float4*)(w_s + (k + 1) * PW + tc * 4);
            float4 w2 = *(const float4*)(w_s + (k + 2) * PW + tc * 4);
            float4 w3 = *(const float4*)(w_s + (k + 3) * PW + tc * 4);
            u64 w0a = pk2(w0.x, w0.y), w0b = pk2(w0.z, w0.w);
            u64 w1a = pk2(w1.x, w1.y), w1b = pk2(w1.z, w1.w);
            u64 w2a = pk2(w2.x, w2.y), w2b = pk2(w2.z, w2.w);
            u64 w3a = pk2(w3.x, w3.y), w3b = pk2(w3.z, w3.w);
#pragma unroll
            for (int i = 0; i < 4; i++) {
                float4 hv = *(const float4*)(h_s + (tn * 4 + i) * PW + k);
                u64 hx = pk2(hv.x, hv.x);
                u64 hy = pk2(hv.y, hv.y);
                u64 hz = pk2(hv.z, hv.z);
                u64 hw = pk2(hv.w, hv.w);
                ffma2(acc2[i][0], hx, w0a); ffma2(acc2[i][1], hx, w0b);
                ffma2(acc2[i][0], hy, w1a); ffma2(acc2[i][1], hy, w1b);
                ffma2(acc2[i][0], hz, w2a); ffma2(acc2[i][1], hz, w2b);
                ffma2(acc2[i][0], hw, w3a); ffma2(acc2[i][1], hw, w3b);
            }
        }
    }

    // epilogue: store feat, compute el/er
    const int head = tc >> 2;
    const int dbase = head * ND + (tc & 3) * 4;
    const float4 al = *(const float4*)(attn_l + dbase);
    const float4 ar = *(const float4*)(attn_r + dbase);

#pragma unroll
    for (int i = 0; i < 4; i++) {
        int node = nb + tn * 4 + i;
        if (node >= N_NODES) continue;
        float4 f;
        upk2(acc2[i][0], f.x, f.y);
        upk2(acc2[i][1], f.z, f.w);
        *(float4*)(g_feat + (size_t)node * HD + tc * 4) = f;

        float pl = f.x * al.x + f.y * al.y + f.z * al.z + f.w * al.w;
        float pr = f.x * ar.x + f.y * ar.y + f.z * ar.z + f.w * ar.w;
        pl += __shfl_xor_sync(0xffffffffu, pl, 1);
        pl += __shfl_xor_sync(0xffffffffu, pl, 2);
        pr += __shfl_xor_sync(0xffffffffu, pr, 1);
        pr += __shfl_xor_sync(0xffffffffu, pr, 2);
        if ((tc & 3) == 0) {
            g_el[node * NH + head] = pl;
            g_er[node * NH + head] = pr;
        }
    }
}

// ---------------- pass 2: fused edge pass ----------------
__global__ __launch_bounds__(256) void k_scatter(const int* __restrict__ src,
                                                 const int* __restrict__ dst) {
    int idx = blockIdx.x * blockDim.x + threadIdx.x;
    int e = idx >> 4;
    if (e >= E_EDGES) return;
    int j  = idx & 15;       // 0..15: head = j>>2, 4 dims each
    int hh = j >> 2;
    int s = __ldg(src + e);
    int d = __ldg(dst + e);

    float x = __ldg(&g_el[s * NH + hh]) + __ldg(&g_er[d * NH + hh]);
    x = (x > 0.0f) ? x : NEG_SLOPE * x;
    float ex = __expf(x);

    if ((j & 3) == 0)
        atomicAdd(&g_den[d * NH + hh], ex);

    float4 f = __ldg((const float4*)(&g_feat[(size_t)s * HD + j * 4]));
    float* p = &g_acc[(size_t)d * HD + j * 4];
    asm volatile("red.global.add.v4.f32 [%0], {%1, %2, %3, %4};"
                 :: "l"(p), "f"(ex * f.x), "f"(ex * f.y), "f"(ex * f.z), "f"(ex * f.w)
                 : "memory");
}

// ---------------- pass 3: normalize + mean over heads (vectorized) ----------------
__global__ void k_final(float* __restrict__ out) {
    int idx = blockIdx.x * blockDim.x + threadIdx.x;
    if (idx >= N_NODES * 4) return;
    int n = idx >> 2;
    int q = idx & 3;                   // dims 4q..4q+3
    float4 den = *(const float4*)(g_den + n * NH);
    float r0 = (den.x > 0.0f) ? (1.0f / den.x) : 0.0f;
    float r1 = (den.y > 0.0f) ? (1.0f / den.y) : 0.0f;
    float r2 = (den.z > 0.0f) ? (1.0f / den.z) : 0.0f;
    float r3 = (den.w > 0.0f) ? (1.0f / den.w) : 0.0f;

    const float* base = g_acc + (size_t)n * HD + q * 4;
    float4 a0 = *(const float4*)(base + 0 * ND);
    float4 a1 = *(const float4*)(base + 1 * ND);
    float4 a2 = *(const float4*)(base + 2 * ND);
    float4 a3 = *(const float4*)(base + 3 * ND);

    float4 r;
    r.x = 0.25f * (a0.x * r0 + a1.x * r1 + a2.x * r2 + a3.x * r3);
    r.y = 0.25f * (a0.y * r0 + a1.y * r1 + a2.y * r2 + a3.y * r3);
    r.z = 0.25f * (a0.z * r0 + a1.z * r1 + a2.z * r2 + a3.z * r3);
    r.w = 0.25f * (a0.w * r0 + a1.w * r1 + a2.w * r2 + a3.w * r3);
    *(float4*)(out + (size_t)n * ND + q * 4) = r;
}

// ---------------- launch ----------------
extern "C" void kernel_launch(void* const* d_in, const int* in_sizes, int n_in,
                              void* d_out, int out_size) {
    const float* h      = (const float*)d_in[0];
    const float* W      = (const float*)d_in[1];
    const float* attn_l = (const float*)d_in[2];
    const float* attn_r = (const float*)d_in[3];
    const int*   src    = (const int*)d_in[4];
    const int*   dst    = (const int*)d_in[5];
    float* out = (float*)d_out;

    k_init   <<<(N_NODES * HD + 255) / 256, 256>>>();
    k_proj   <<<(N_NODES + MT - 1) / MT, 256>>>(h, W, attn_l, attn_r);
    k_scatter<<<(E_EDGES * 16 + 255) / 256, 256>>>(src, dst);
    k_final  <<<(N_NODES * 4 + 255) / 256, 256>>>(out);
}